// round 3
// baseline (speedup 1.0000x reference)
#include <cuda_runtime.h>
#include <math.h>
#include <stdint.h>

constexpr long MTOK  = 16 * 512;     // 8192 tokens

// ---------------------------------------------------------------------------
// Scratch arena
// ---------------------------------------------------------------------------
constexpr long OFF_X    = 0;
constexpr long OFF_LN   = OFF_X    + MTOK * 256;
constexpr long OFF_B256 = OFF_LN   + MTOK * 256;
constexpr long OFF_U    = OFF_B256 + MTOK * 256;
constexpr long OFF_XZ   = OFF_U    + 2 * MTOK * 128;
constexpr long OFF_XC   = OFF_XZ   + 2 * MTOK * 512;
constexpr long OFF_DBC  = OFF_XC   + 2 * MTOK * 256;
constexpr long OFF_DT   = OFF_DBC  + 2 * MTOK * 40;
constexpr long OFF_Y    = OFF_DT   + 2 * MTOK * 256;
constexpr long OFF_CAT  = OFF_Y    + 2 * MTOK * 256;
constexpr long OFF_FF   = OFF_CAT  + MTOK * 256;
constexpr long TOTAL_F  = OFF_FF   + MTOK * 1024;

__device__ float g_buf[TOTAL_F];

__device__ __forceinline__ uint32_t smem_u32(const void* p)
{
    return (uint32_t)__cvta_generic_to_shared(p);
}

// ---------------------------------------------------------------------------
// Block-wide sum over 256 threads
// ---------------------------------------------------------------------------
__device__ __forceinline__ float blockSum256(float v, float* sbuf)
{
#pragma unroll
    for (int o = 16; o > 0; o >>= 1)
        v += __shfl_xor_sync(0xffffffffu, v, o);
    __syncthreads();
    if ((threadIdx.x & 31) == 0) sbuf[threadIdx.x >> 5] = v;
    __syncthreads();
    float s = sbuf[0];
#pragma unroll
    for (int i = 1; i < 8; i++) s += sbuf[i];
    return s;
}

// ---------------------------------------------------------------------------
// Embedding: x = LN(ids @ proj_w + proj_b)
// ---------------------------------------------------------------------------
__global__ void embed_ln_kernel(const float* __restrict__ ids,
                                const float* __restrict__ pw,
                                const float* __restrict__ pb,
                                const float* __restrict__ gam,
                                const float* __restrict__ bet,
                                float* __restrict__ x)
{
    __shared__ float sin[32];
    __shared__ float sred[8];
    int m = blockIdx.x, d = threadIdx.x;
    if (d < 32) sin[d] = ids[(long)m * 32 + d];
    __syncthreads();
    float v = pb[d];
#pragma unroll
    for (int e = 0; e < 32; e++)
        v = fmaf(sin[e], pw[e * 256 + d], v);
    float mean = blockSum256(v, sred) * (1.f / 256.f);
    float c = v - mean;
    float var = blockSum256(c * c, sred) * (1.f / 256.f);
    x[(long)m * 256 + d] = c * rsqrtf(var + 1e-5f) * gam[d] + bet[d];
}

// ---------------------------------------------------------------------------
// LayerNorm over D=256, optional residual
// ---------------------------------------------------------------------------
__global__ void ln_kernel(const float* __restrict__ in,
                          const float* __restrict__ res,
                          const float* __restrict__ gam,
                          const float* __restrict__ bet,
                          float* __restrict__ out)
{
    __shared__ float sred[8];
    int m = blockIdx.x, d = threadIdx.x;
    float v = in[(long)m * 256 + d];
    if (res) v += res[(long)m * 256 + d];
    float mean = blockSum256(v, sred) * (1.f / 256.f);
    float c = v - mean;
    float var = blockSum256(c * c, sred) * (1.f / 256.f);
    out[(long)m * 256 + d] = c * rsqrtf(var + 1e-5f) * gam[d] + bet[d];
}

// ---------------------------------------------------------------------------
// TF32 tensor-core GEMM, cp.async double-buffered.
// M%128==0, N%128==0, K%16==0, lda==K. Raw fp32 bits fed to tf32 mma
// (hardware truncates the low 13 mantissa bits).
// act: 0=none, 2=exact GELU
// storeMode: 0=plain C (+g*sCg), 1=split+reverse into U, 2=concat+unreverse into CAT
// ---------------------------------------------------------------------------
__global__ void __launch_bounds__(256)
tf32gemm_kernel(const float* __restrict__ A,
                const float* __restrict__ W,
                const float* __restrict__ bias,
                float* __restrict__ C,
                int M, int N, int K, int act, int storeMode,
                long sAg, long sWg, long sCg)
{
    int g = blockIdx.z;
    A += (long)g * sAg;
    W += (long)g * sWg;
    if (storeMode == 0) C += (long)g * sCg;

    __shared__ float As[2][128][20];    // [buf][m][k] pad 16->20
    __shared__ float Bs[2][16][136];    // [buf][k][n] pad 128->136

    int tid  = threadIdx.x;
    int warp = tid >> 5;
    int lane = tid & 31;
    int wm = (warp & 1) * 64;
    int wn = (warp >> 1) * 32;
    int gID = lane >> 2;
    int tig = lane & 3;
    int rowBase = blockIdx.y * 128;
    int colBase = blockIdx.x * 128;

    const float* Abase = A + (long)rowBase * K;
    const float* Wbase = W + colBase;

    float acc[4][4][4];
#pragma unroll
    for (int a = 0; a < 4; a++)
#pragma unroll
        for (int b = 0; b < 4; b++)
#pragma unroll
            for (int c = 0; c < 4; c++) acc[a][b][c] = 0.f;

    // async stage of one 128x16 A slab + 16x128 B slab
    auto stage = [&](int buf, int k0) {
#pragma unroll
        for (int it = 0; it < 2; it++) {
            int idx = tid + it * 256;          // 0..511
            int r  = idx >> 2;
            int c4 = (idx & 3) * 4;
            uint32_t s = smem_u32(&As[buf][r][c4]);
            const float* gp = Abase + (long)r * K + k0 + c4;
            asm volatile("cp.async.cg.shared.global [%0], [%1], 16;\n"
                         :: "r"(s), "l"(gp));
        }
#pragma unroll
        for (int it = 0; it < 2; it++) {
            int idx = tid + it * 256;
            int kr = idx >> 5;
            int n4 = (idx & 31) * 4;
            uint32_t s = smem_u32(&Bs[buf][kr][n4]);
            const float* gp = Wbase + (long)(k0 + kr) * N + n4;
            asm volatile("cp.async.cg.shared.global [%0], [%1], 16;\n"
                         :: "r"(s), "l"(gp));
        }
        asm volatile("cp.async.commit_group;\n");
    };

    auto compute = [&](int buf) {
#pragma unroll
        for (int ks = 0; ks < 16; ks += 8) {
            uint32_t bf[4][2];
#pragma unroll
            for (int nt = 0; nt < 4; nt++) {
                int col = wn + nt * 8 + gID;
                bf[nt][0] = __float_as_uint(Bs[buf][ks + tig][col]);
                bf[nt][1] = __float_as_uint(Bs[buf][ks + tig + 4][col]);
            }
#pragma unroll
            for (int mt = 0; mt < 4; mt++) {
                int row = wm + mt * 16 + gID;
                uint32_t a0 = __float_as_uint(As[buf][row][ks + tig]);
                uint32_t a1 = __float_as_uint(As[buf][row + 8][ks + tig]);
                uint32_t a2 = __float_as_uint(As[buf][row][ks + tig + 4]);
                uint32_t a3 = __float_as_uint(As[buf][row + 8][ks + tig + 4]);
#pragma unroll
                for (int nt = 0; nt < 4; nt++) {
                    asm volatile(
                        "mma.sync.aligned.m16n8k8.row.col.f32.tf32.tf32.f32 "
                        "{%0,%1,%2,%3}, {%4,%5,%6,%7}, {%8,%9}, {%0,%1,%2,%3};\n"
                        : "+f"(acc[mt][nt][0]), "+f"(acc[mt][nt][1]),
                          "+f"(acc[mt][nt][2]), "+f"(acc[mt][nt][3])
                        : "r"(a0), "r"(a1), "r"(a2), "r"(a3),
                          "r"(bf[nt][0]), "r"(bf[nt][1]));
                }
            }
        }
    };

    stage(0, 0);
    int buf = 0;
    for (int k0 = 16; k0 < K; k0 += 16) {
        stage(buf ^ 1, k0);
        asm volatile("cp.async.wait_group 1;\n");
        __syncthreads();
        compute(buf);
        __syncthreads();
        buf ^= 1;
    }
    asm volatile("cp.async.wait_group 0;\n");
    __syncthreads();
    compute(buf);

    // epilogue
#pragma unroll
    for (int mt = 0; mt < 4; mt++) {
        int row0 = rowBase + wm + mt * 16 + gID;
#pragma unroll
        for (int nt = 0; nt < 4; nt++) {
            int col = colBase + wn + nt * 8 + tig * 2;
            float b0 = 0.f, b1 = 0.f;
            if (bias) { b0 = bias[col]; b1 = bias[col + 1]; }
            float v[4];
            v[0] = acc[mt][nt][0] + b0;
            v[1] = acc[mt][nt][1] + b1;
            v[2] = acc[mt][nt][2] + b0;
            v[3] = acc[mt][nt][3] + b1;
            if (act == 2) {
#pragma unroll
                for (int q = 0; q < 4; q++)
                    v[q] = 0.5f * v[q] * (1.f + erff(v[q] * 0.70710678118654752f));
            }
#pragma unroll
            for (int h = 0; h < 2; h++) {
                int row = row0 + h * 8;
                float2 val = make_float2(v[h * 2], v[h * 2 + 1]);
                if (storeMode == 0) {
                    *(float2*)&C[(long)row * N + col] = val;
                } else if (storeMode == 1) {
                    // split + reverse: cols<128 -> U0[row], cols>=128 -> U1 reversed
                    if (col < 128) {
                        *(float2*)&C[(long)row * 128 + col] = val;
                    } else {
                        long b = row >> 9, t = row & 511;
                        *(float2*)&C[MTOK * 128 + ((b << 9) + 511 - t) * 128 + (col - 128)] = val;
                    }
                } else {
                    // concat + un-reverse (N==128, batched g)
                    if (g == 0) {
                        *(float2*)&C[(long)row * 256 + col] = val;
                    } else {
                        long b = row >> 9, t = row & 511;
                        *(float2*)&C[((b << 9) + 511 - t) * 256 + 128 + col] = val;
                    }
                }
            }
        }
    }
}

// ---------------------------------------------------------------------------
// fp32 fallback SGEMM (N=40 / K=8 GEMMs): C = act(A @ W + bias)
// act: 0=none, 1=softplus
// ---------------------------------------------------------------------------
__global__ void sgemm_kernel(const float* __restrict__ A,
                             const float* __restrict__ W,
                             const float* __restrict__ bias,
                             float* __restrict__ C,
                             int M, int N, int K, int lda, int act,
                             long sAg, long sWg, long sCg, long sBg)
{
    int g = blockIdx.z;
    A += (long)g * sAg;
    W += (long)g * sWg;
    C += (long)g * sCg;
    if (bias) bias += (long)g * sBg;

    __shared__ __align__(16) float As[16][128];
    __shared__ __align__(16) float Ws[16][64];

    int tid = threadIdx.x;
    int tx = tid & 15;
    int ty = tid >> 4;
    int rowBase = blockIdx.y * 128;
    int colBase = blockIdx.x * 64;

    float acc[8][4];
#pragma unroll
    for (int i = 0; i < 8; i++)
#pragma unroll
        for (int j = 0; j < 4; j++) acc[i][j] = 0.f;

    for (int k0 = 0; k0 < K; k0 += 16) {
#pragma unroll
        for (int it = 0; it < 8; it++) {
            int idx = tid + it * 256;
            int m = idx >> 4;
            int kk = idx & 15;
            int gr = rowBase + m, gk = k0 + kk;
            As[kk][m] = (gr < M && gk < K) ? A[(long)gr * lda + gk] : 0.f;
        }
#pragma unroll
        for (int it = 0; it < 4; it++) {
            int idx = tid + it * 256;
            int kk = idx >> 6;
            int n = idx & 63;
            int gk = k0 + kk, gn = colBase + n;
            Ws[kk][n] = (gk < K && gn < N) ? W[(long)gk * N + gn] : 0.f;
        }
        __syncthreads();
#pragma unroll
        for (int k = 0; k < 16; k++) {
            float a[8], w[4];
            float4 a0 = *(const float4*)&As[k][ty * 8];
            float4 a1 = *(const float4*)&As[k][ty * 8 + 4];
            a[0] = a0.x; a[1] = a0.y; a[2] = a0.z; a[3] = a0.w;
            a[4] = a1.x; a[5] = a1.y; a[6] = a1.z; a[7] = a1.w;
            float4 w0 = *(const float4*)&Ws[k][tx * 4];
            w[0] = w0.x; w[1] = w0.y; w[2] = w0.z; w[3] = w0.w;
#pragma unroll
            for (int i = 0; i < 8; i++)
#pragma unroll
                for (int j = 0; j < 4; j++)
                    acc[i][j] = fmaf(a[i], w[j], acc[i][j]);
        }
        __syncthreads();
    }

#pragma unroll
    for (int i = 0; i < 8; i++) {
        int gr = rowBase + ty * 8 + i;
        if (gr >= M) continue;
#pragma unroll
        for (int j = 0; j < 4; j++) {
            int gn = colBase + tx * 4 + j;
            if (gn >= N) continue;
            float v = acc[i][j];
            if (bias) v += bias[gn];
            if (act == 1) v = (v > 20.f) ? v : log1pf(expf(v));
            C[(long)gr * N + gn] = v;
        }
    }
}

// ---------------------------------------------------------------------------
// depthwise causal conv (K=4) + bias + silu
// ---------------------------------------------------------------------------
__global__ void conv_silu_kernel(const float* __restrict__ xz,
                                 const float* __restrict__ convw,
                                 const float* __restrict__ convb,
                                 float* __restrict__ xc)
{
    long i = (long)blockIdx.x * 256 + threadIdx.x;
    if (i >= 2 * MTOK * 256) return;
    int d = (int)(i & 255);
    long gm = i >> 8;
    int g = (int)(gm / MTOK);
    long m = gm % MTOK;
    int t = (int)(m & 511);

    const float* w = convw + ((long)g * 256 + d) * 4;
    const float* xp = xz + ((long)g * MTOK + m) * 512 + d;
    float acc = convb[(long)g * 256 + d];
#pragma unroll
    for (int k = 0; k < 4; k++) {
        int tt = t - 3 + k;
        if (tt >= 0) acc = fmaf(xp[(long)(k - 3) * 512], w[k], acc);
    }
    xc[i] = acc / (1.f + __expf(-acc));
}

// ---------------------------------------------------------------------------
// Selective scan (+ fused output gate y *= silu(z))
// 16-lane group per (g, b, d); lane = n
// ---------------------------------------------------------------------------
__global__ void scan_kernel(const float* __restrict__ dt,
                            const float* __restrict__ xc,
                            const float* __restrict__ dbc,
                            const float* __restrict__ xz,
                            const float* __restrict__ alog,
                            const float* __restrict__ dpar,
                            float* __restrict__ y)
{
    int grp = blockIdx.x * 16 + (threadIdx.x >> 4);
    int n = threadIdx.x & 15;
    int g = grp >> 12;
    int bd = grp & 4095;
    int b = bd >> 8;
    int d = bd & 255;

    float A = -__expf(alog[((long)(g * 256 + d)) * 16 + n]);
    float dp = dpar[(long)g * 256 + d];

    long mbase = (long)g * MTOK + (long)b * 512;
    const float* dtp = dt + mbase * 256 + d;
    const float* xcp = xc + mbase * 256 + d;
    const float* dbp = dbc + mbase * 40;
    const float* zp  = xz + mbase * 512 + 256 + d;
    float* yp = y + mbase * 256 + d;

    float h = 0.f;
    for (int t = 0; t < 512; t++) {
        float dtv = dtp[(long)t * 256];
        float xv = xcp[(long)t * 256];
        float Bn = dbp[(long)t * 40 + 8 + n];
        float Cn = dbp[(long)t * 40 + 24 + n];
        h = __expf(dtv * A) * h + dtv * Bn * xv;
        float p = h * Cn;
        p += __shfl_xor_sync(0xffffffffu, p, 8);
        p += __shfl_xor_sync(0xffffffffu, p, 4);
        p += __shfl_xor_sync(0xffffffffu, p, 2);
        p += __shfl_xor_sync(0xffffffffu, p, 1);
        if (n == 0) {
            float z = zp[(long)t * 512];
            float sz = z / (1.f + __expf(-z));
            yp[(long)t * 256] = (p + dp * xv) * sz;
        }
    }
}

// ---------------------------------------------------------------------------
// Launch helpers
// ---------------------------------------------------------------------------
static void launch_tf32(const float* A, const float* W, const float* bias, float* C,
                        int M, int N, int K, int act, int storeMode, int G,
                        long sAg, long sWg, long sCg)
{
    dim3 grid(N / 128, M / 128, G);
    tf32gemm_kernel<<<grid, 256>>>(A, W, bias, C, M, N, K, act, storeMode, sAg, sWg, sCg);
}

static void launch_sgemm(const float* A, const float* W, const float* bias, float* C,
                         int M, int N, int K, int lda, int act, int G,
                         long sAg, long sWg, long sCg, long sBg)
{
    dim3 grid((N + 63) / 64, (M + 127) / 128, G);
    sgemm_kernel<<<grid, 256>>>(A, W, bias, C, M, N, K, lda, act, sAg, sWg, sCg, sBg);
}

extern "C" void kernel_launch(void* const* d_in, const int* in_sizes, int n_in,
                              void* d_out, int out_size)
{
    const float* input_ids = (const float*)d_in[0];
    const float* proj_w    = (const float*)d_in[1];
    const float* proj_b    = (const float*)d_in[2];
    const float* ln0_g     = (const float*)d_in[3];
    const float* ln0_b     = (const float*)d_in[4];
    const float* ln1_g     = (const float*)d_in[5];
    const float* ln1_b     = (const float*)d_in[6];
    const float* ip_w      = (const float*)d_in[7];
    const float* ip_b      = (const float*)d_in[8];
    const float* s_inw     = (const float*)d_in[9];
    const float* s_convw   = (const float*)d_in[10];
    const float* s_convb   = (const float*)d_in[11];
    const float* s_xw      = (const float*)d_in[12];
    const float* s_dtw     = (const float*)d_in[13];
    const float* s_dtb     = (const float*)d_in[14];
    const float* s_alog    = (const float*)d_in[15];
    const float* s_d       = (const float*)d_in[16];
    const float* s_outw    = (const float*)d_in[17];
    const float* op_w      = (const float*)d_in[18];
    const float* op_b      = (const float*)d_in[19];
    const float* ln2_g     = (const float*)d_in[20];
    const float* ln2_b     = (const float*)d_in[21];
    const float* f_w1      = (const float*)d_in[22];
    const float* f_b1      = (const float*)d_in[23];
    const float* f_w2      = (const float*)d_in[24];
    const float* f_b2      = (const float*)d_in[25];
    const float* ln3_g     = (const float*)d_in[26];
    const float* ln3_b     = (const float*)d_in[27];

    float* base = nullptr;
    cudaGetSymbolAddress((void**)&base, g_buf);

    float* X    = base + OFF_X;
    float* LNb  = base + OFF_LN;
    float* B256 = base + OFF_B256;
    float* U    = base + OFF_U;
    float* XZ   = base + OFF_XZ;
    float* XC   = base + OFF_XC;
    float* DBC  = base + OFF_DBC;
    float* DT   = base + OFF_DT;
    float* Y    = base + OFF_Y;
    float* CAT  = base + OFF_CAT;
    float* FF   = base + OFF_FF;

    const int M = (int)MTOK;
    const long EW2 = 2 * MTOK * 256;
    const int EW2_BLOCKS = (int)((EW2 + 255) / 256);

    embed_ln_kernel<<<M, 256>>>(input_ids, proj_w, proj_b, ln0_g, ln0_b, X);

    for (int l = 0; l < 12; l++) {
        // LN1
        ln_kernel<<<M, 256>>>(X, nullptr, ln1_g + l * 256, ln1_b + l * 256, LNb);
        // in-proj -> fused split+reverse into U
        launch_tf32(LNb, ip_w + (long)l * 256 * 256, ip_b + l * 256, U,
                    M, 256, 256, 0, 1, 1, 0, 0, 0);
        // xz = u @ inw (batched 2)
        launch_tf32(U, s_inw + (long)l * 2 * 128 * 512, nullptr, XZ,
                    M, 512, 128, 0, 0, 2, MTOK * 128, 128 * 512, MTOK * 512);
        // conv + silu
        conv_silu_kernel<<<EW2_BLOCKS, 256>>>(XZ, s_convw + (long)l * 2 * 256 * 4,
                                              s_convb + (long)l * 2 * 256, XC);
        // dbc = xc @ xw (fp32, N=40)
        launch_sgemm(XC, s_xw + (long)l * 2 * 256 * 40, nullptr, DBC,
                     M, 40, 256, 256, 0, 2, MTOK * 256, 256 * 40, MTOK * 40, 0);
        // dt = softplus(dbc[:, :8] @ dtw + dtb)
        launch_sgemm(DBC, s_dtw + (long)l * 2 * 8 * 256, s_dtb + (long)l * 2 * 256, DT,
                     M, 256, 8, 40, 1, 2, MTOK * 40, 8 * 256, MTOK * 256, 256);
        // selective scan + fused silu(z) gate
        scan_kernel<<<512, 256>>>(DT, XC, DBC, XZ,
                                  s_alog + (long)l * 2 * 256 * 16,
                                  s_d + (long)l * 2 * 256, Y);
        // so = y @ outw (batched 2) -> fused concat+unreverse into CAT
        launch_tf32(Y, s_outw + (long)l * 2 * 256 * 128, nullptr, CAT,
                    M, 128, 256, 0, 2, 2, MTOK * 256, 256 * 128, 0);
        // out-proj
        launch_tf32(CAT, op_w + (long)l * 256 * 256, op_b + l * 256, B256,
                    M, 256, 256, 0, 0, 1, 0, 0, 0);
        // LN2 (residual)
        ln_kernel<<<M, 256>>>(B256, X, ln2_g + l * 256, ln2_b + l * 256, X);
        // ff = gelu(x @ w1 + b1)
        launch_tf32(X, f_w1 + (long)l * 256 * 1024, f_b1 + l * 1024, FF,
                    M, 1024, 256, 2, 0, 1, 0, 0, 0);
        // f = ff @ w2 + b2
        launch_tf32(FF, f_w2 + (long)l * 1024 * 256, f_b2 + l * 256, B256,
                    M, 256, 1024, 0, 0, 1, 0, 0, 0);
        // LN3 (residual); last layer -> d_out
        float* dst = (l == 11) ? (float*)d_out : X;
        ln_kernel<<<M, 256>>>(B256, X, ln3_g + l * 256, ln3_b + l * 256, dst);
    }
}